// round 3
// baseline (speedup 1.0000x reference)
#include <cuda_runtime.h>

#define BN 1024
#define CN 128
#define DN 16
#define SN 4
#define K3C 23
#define K2C 5
#define K1C 2

// ---------------- scratch (no allocations allowed) ----------------
__device__ float g_uw3[(size_t)SN * CN * 1024 * 16]; // [e][c][m][l], m = oc*256+i*16+j  (32MB)
__device__ float g_uw2[(size_t)SN * CN * 1024];      // [e][c][m]
__device__ float g_uw1[(size_t)SN * CN * 64];        // [e][c][oc*16+i]
__device__ int   g_sorted[BN];
__device__ int   g_off[SN + 1];
__device__ float g_y[(size_t)BN * CN * 4];           // [b][c][oc]

// ---------------- kernel 1: UW3[e,c,m,l] = sum_k u3[.]*w3[br,e,k,c] ----------------
// grid (128 ml-tiles, 2 c-halves), 128 threads
__global__ void k_uw3(const float* __restrict__ u3_0, const float* __restrict__ u3_1,
                      const float* __restrict__ w3) {
    __shared__ float s_w3[2 * K3C * CN]; // [br][k][c], 5888 floats
    const int tid = threadIdx.x;
    const int ml  = blockIdx.x * 128 + tid;      // 0..16383
    const int c0  = blockIdx.y * 64;
    const int l = ml & 15, m = ml >> 4;
    const int j = m & 15, i = (m >> 4) & 15, oc = m >> 8;
    const int br = (oc > 0) ? 1 : 0;

    const float* up = (oc == 0)
        ? (u3_0 + ((i * 16 + j) * 16 + l) * K3C)
        : (u3_1 + ((((oc - 1) * 16 + i) * 16 + j) * 16 + l) * K3C);
    float u3r[K3C];
#pragma unroll
    for (int k = 0; k < K3C; k++) u3r[k] = up[k];

    for (int e = 0; e < SN; e++) {
        __syncthreads();
        for (int idx = tid; idx < 2 * K3C * CN; idx += 128) {
            int brr = idx / (K3C * 128);
            int rem = idx - brr * (K3C * 128);
            int k = rem >> 7, cc = rem & 127;
            s_w3[idx] = w3[(((size_t)(brr * 4 + e) * K3C + k) * 128) + cc];
        }
        __syncthreads();
        const float* wp = s_w3 + br * (K3C * 128);
        float* outp = g_uw3 + ((size_t)e * 128) * 16384 + ml;
        for (int c = c0; c < c0 + 64; c += 4) {
            float a0 = 0.f, a1 = 0.f, a2 = 0.f, a3 = 0.f;
#pragma unroll
            for (int k = 0; k < K3C; k++) {
                float4 w = *(const float4*)(wp + k * 128 + c);
                a0 = fmaf(u3r[k], w.x, a0);
                a1 = fmaf(u3r[k], w.y, a1);
                a2 = fmaf(u3r[k], w.z, a2);
                a3 = fmaf(u3r[k], w.w, a3);
            }
            outp[(size_t)(c + 0) * 16384] = a0;
            outp[(size_t)(c + 1) * 16384] = a1;
            outp[(size_t)(c + 2) * 16384] = a2;
            outp[(size_t)(c + 3) * 16384] = a3;
        }
    }
}

// ---------------- kernel 2: UW2 / UW1 folds ----------------
// grid 512 (e*128+c), 128 threads
__global__ void k_uw21(const float* __restrict__ u2_0, const float* __restrict__ u2_1,
                       const float* __restrict__ u1_0, const float* __restrict__ u1_1,
                       const float* __restrict__ w2, const float* __restrict__ w1) {
    const int ec = blockIdx.x;
    const int e = ec >> 7, c = ec & 127;
    const int tid = threadIdx.x;
    for (int m = tid; m < 1024; m += 128) {
        int j = m & 15, i = (m >> 4) & 15, oc = m >> 8;
        int br = (oc > 0) ? 1 : 0;
        int o1 = br ? (oc - 1) : 0;
        const float* up = br ? (u2_1 + ((o1 * 16 + i) * 16 + j) * K2C)
                             : (u2_0 + (i * 16 + j) * K2C);
        float acc = 0.f;
#pragma unroll
        for (int k = 0; k < K2C; k++)
            acc = fmaf(up[k], w2[((size_t)((br * 4 + e) * K2C + k)) * 128 + c], acc);
        g_uw2[(size_t)ec * 1024 + m] = acc;
    }
    if (tid < 64) {
        int m = tid;
        int i = m & 15, oc = m >> 4;
        int br = (oc > 0) ? 1 : 0;
        int o1 = br ? (oc - 1) : 0;
        const float* up = br ? (u1_1 + (o1 * 16 + i) * K1C) : (u1_0 + i * K1C);
        float acc = 0.f;
#pragma unroll
        for (int k = 0; k < K1C; k++)
            acc = fmaf(up[k], w1[((size_t)((br * 4 + e) * K1C + k)) * 128 + c], acc);
        g_uw1[(size_t)ec * 64 + m] = acc;
    }
}

// ---------------- kernel 3: counting sort by species ----------------
__global__ void k_sort(const int* __restrict__ species) {
    __shared__ int cnt[SN], cur[SN], off[SN + 1];
    const int tid = threadIdx.x; // 1024
    if (tid < SN) { cnt[tid] = 0; cur[tid] = 0; }
    __syncthreads();
    int s = species[tid];
    atomicAdd(&cnt[s], 1);
    __syncthreads();
    if (tid == 0) {
        off[0] = 0;
        for (int e = 0; e < SN; e++) off[e + 1] = off[e] + cnt[e];
        for (int e = 0; e <= SN; e++) g_off[e] = off[e];
    }
    __syncthreads();
    int pos = off[s] + atomicAdd(&cur[s], 1);
    g_sorted[pos] = tid;
}

// ---------------- kernel 4: main polynomial contraction ----------------
// grid (c=128, e=4), 320 threads, dyn smem = (16384+1024+64+16*320)*4 = 90368 B
#define TMAIN 320
__global__ __launch_bounds__(TMAIN, 2) void k_main(const float* __restrict__ xg) {
    extern __shared__ float smem[];
    float* sUW3 = smem;                 // 16384
    float* sUW2 = sUW3 + 16384;         // 1024
    float* sUW1 = sUW2 + 1024;          // 64
    float* sX   = sUW1 + 64;            // [i][tid] : i*TMAIN + tid (5120)

    const int c = blockIdx.x, e = blockIdx.y;
    const int tid = threadIdx.x;
    const size_t ec = (size_t)(e * 128 + c);

    {
        const float4* g3 = (const float4*)(g_uw3 + ec * 16384);
        float4* s3 = (float4*)sUW3;
        for (int idx = tid; idx < 4096; idx += TMAIN) s3[idx] = g3[idx];
        if (tid < 256) ((float4*)sUW2)[tid] = ((const float4*)(g_uw2 + ec * 1024))[tid];
        if (tid < 16)  ((float4*)sUW1)[tid] = ((const float4*)(g_uw1 + ec * 64))[tid];
    }
    const int lo = g_off[e], hi = g_off[e + 1];
    __syncthreads();

    for (int t = lo + tid; t < hi; t += TMAIN) {
        const int b = g_sorted[t];
        const float* xp = xg + ((size_t)b * 128 + c) * 16;
        float x[16];
#pragma unroll
        for (int q = 0; q < 4; q++) {
            float4 v = ((const float4*)xp)[q];
            x[4 * q + 0] = v.x; x[4 * q + 1] = v.y; x[4 * q + 2] = v.z; x[4 * q + 3] = v.w;
        }
#pragma unroll
        for (int q = 0; q < 16; q++) sX[q * TMAIN + tid] = x[q];

        float* yout = g_y + ((size_t)b * 128 + c) * 4;
#pragma unroll 1
        for (int oc = 0; oc < 4; oc++) {
            const float* b3 = sUW3 + oc * 4096;
            const float* b2 = sUW2 + oc * 256;
            const float* b1 = sUW1 + oc * 16;
            float yo = 0.f;
#pragma unroll 1
            for (int i = 0; i < 16; i++) {
                const float* r3 = b3 + i * 256;
                const float* r2 = b2 + i * 16;
                float uw2v[16];
#pragma unroll
                for (int q = 0; q < 4; q++) {
                    float4 v = ((const float4*)r2)[q];
                    uw2v[4 * q + 0] = v.x; uw2v[4 * q + 1] = v.y;
                    uw2v[4 * q + 2] = v.z; uw2v[4 * q + 3] = v.w;
                }
                float accA = 0.f, accB = 0.f;
#pragma unroll
                for (int j = 0; j < 16; j++) {
                    const float4* p = (const float4*)(r3 + j * 16);
                    float4 a = p[0], bb = p[1], c4 = p[2], d4 = p[3];
                    float s0 = fmaf(a.x, x[0], uw2v[j]);
                    float s1 = a.y * x[1];
                    float s2 = a.z * x[2];
                    float s3 = a.w * x[3];
                    s0 = fmaf(bb.x, x[4], s0);
                    s1 = fmaf(bb.y, x[5], s1);
                    s2 = fmaf(bb.z, x[6], s2);
                    s3 = fmaf(bb.w, x[7], s3);
                    s0 = fmaf(c4.x, x[8], s0);
                    s1 = fmaf(c4.y, x[9], s1);
                    s2 = fmaf(c4.z, x[10], s2);
                    s3 = fmaf(c4.w, x[11], s3);
                    s0 = fmaf(d4.x, x[12], s0);
                    s1 = fmaf(d4.y, x[13], s1);
                    s2 = fmaf(d4.z, x[14], s2);
                    s3 = fmaf(d4.w, x[15], s3);
                    float s = (s0 + s1) + (s2 + s3);
                    if (j & 1) accB = fmaf(s, x[j], accB);
                    else       accA = fmaf(s, x[j], accA);
                }
                float acc = (accA + accB) + b1[i];
                yo = fmaf(acc, sX[i * TMAIN + tid], yo);
            }
            yout[oc] = yo;
        }
    }
}

// ---------------- kernel 5: irrep-wise linear + flatten ----------------
// grid 128 blocks, 128 threads, 8 nodes per block
__global__ void k_lin(const float* __restrict__ wl, float* __restrict__ out) {
    __shared__ float sY[8 * 512]; // 16KB
    const int tid = threadIdx.x;
    const int b0 = blockIdx.x * 8;
#pragma unroll
    for (int it = 0; it < 8; it++)
        ((float4*)sY)[tid + it * 128] = ((const float4*)(g_y + (size_t)b0 * 512))[tid + it * 128];
    __syncthreads();

    const int n = tid;
    float acc[8][4];
#pragma unroll
    for (int bb = 0; bb < 8; bb++)
#pragma unroll
        for (int o = 0; o < 4; o++) acc[bb][o] = 0.f;

    for (int cc = 0; cc < 128; cc++) {
        float w0  = wl[cc * 128 + n];           // w_lin[0][cc][n]
        float w1v = wl[16384 + cc * 128 + n];   // w_lin[1][cc][n]
#pragma unroll
        for (int bb = 0; bb < 8; bb++) {
            float4 yv = *(const float4*)(sY + bb * 512 + cc * 4);
            acc[bb][0] = fmaf(yv.x, w0,  acc[bb][0]);
            acc[bb][1] = fmaf(yv.y, w1v, acc[bb][1]);
            acc[bb][2] = fmaf(yv.z, w1v, acc[bb][2]);
            acc[bb][3] = fmaf(yv.w, w1v, acc[bb][3]);
        }
    }
    const float scale = 0.08838834764831843f; // 1/sqrt(128)
#pragma unroll
    for (int bb = 0; bb < 8; bb++) {
        float* op = out + (size_t)(b0 + bb) * 512;
        op[n]               = acc[bb][0] * scale;
        op[128 + n * 3 + 0] = acc[bb][1] * scale;
        op[128 + n * 3 + 1] = acc[bb][2] * scale;
        op[128 + n * 3 + 2] = acc[bb][3] * scale;
    }
}

// ---------------- launch ----------------
extern "C" void kernel_launch(void* const* d_in, const int* in_sizes, int n_in,
                              void* d_out, int out_size) {
    const float* node_feats = (const float*)d_in[0];
    const float* u3_0 = (const float*)d_in[1];
    const float* u3_1 = (const float*)d_in[2];
    const float* u2_0 = (const float*)d_in[3];
    const float* u2_1 = (const float*)d_in[4];
    const float* u1_0 = (const float*)d_in[5];
    const float* u1_1 = (const float*)d_in[6];
    const float* w3   = (const float*)d_in[7];
    const float* w2   = (const float*)d_in[8];
    const float* w1   = (const float*)d_in[9];
    const float* wlin = (const float*)d_in[10];
    const int*   spec = (const int*)d_in[11];
    float* out = (float*)d_out;

    const int smem_main = (16384 + 1024 + 64 + 16 * TMAIN) * 4; // 90368 B
    cudaFuncSetAttribute(k_main, cudaFuncAttributeMaxDynamicSharedMemorySize, smem_main);

    k_uw3<<<dim3(128, 2), 128>>>(u3_0, u3_1, w3);
    k_uw21<<<512, 128>>>(u2_0, u2_1, u1_0, u1_1, w2, w1);
    k_sort<<<1, 1024>>>(spec);
    k_main<<<dim3(128, 4), TMAIN, smem_main>>>(node_feats);
    k_lin<<<128, 128>>>(wlin, out);
}